// round 17
// baseline (speedup 1.0000x reference)
#include <cuda_runtime.h>
#include <cstdint>
#include <math.h>

#define D_MODEL     2048
#define NUM_EXPERTS 64
#define N_TOKENS    16384
#define BM          128                 // tokens per CTA
#define BK          32                  // K per chunk
#define NCHUNK      (D_MODEL / BK)      // 64
#define THREADS     256                 // 8 warps x 16 tokens
#define ROWB        160                 // bytes per smem row (128 data + 32 pad)
#define GAP_THRESH  4e-3f               // >5x max tf32 GEMM error tail
#define LSTRIDE     65

// smem: bias 256B | double-buffered {As 128x160, Bs 64x160}
#define SM_BIAS     0
#define SM_BUF      256
#define ASIZE       (BM * ROWB)                       // 20480
#define BUFSTRIDE   (ASIZE + NUM_EXPERTS * ROWB)      // 30720
#define SM_FLAGS    (SM_BUF + BM * LSTRIDE * 4)       // 33536
#define SMEM_TOTAL  (SM_BUF + 2 * BUFSTRIDE)          // 61696

// W pre-rounded to tf32 and pair-interleaved:
// gW2[((c*64+e)*16 + p)] = {W[e][c*32+s*8+j], W[e][c*32+s*8+j+4]} , p = s*4+j
__device__ float2 gW2[NCHUNK * NUM_EXPERTS * 16];

// ---------------------------------------------------------------------------
static __device__ __forceinline__ uint32_t tf32_rna(float x) {
    uint32_t r;
    asm("cvt.rna.tf32.f32 %0, %1;" : "=r"(r) : "f"(x));
    return r;
}
static __device__ __forceinline__ uint2 lds_u2(const char* base, int row, int p) {
    return *(const uint2*)(base + row * ROWB + p * 8);
}
static __device__ __forceinline__ void mma_tf32(float* d,
                                                uint32_t a0, uint32_t a1,
                                                uint32_t a2, uint32_t a3,
                                                uint32_t b0, uint32_t b1) {
    asm volatile(
        "mma.sync.aligned.m16n8k8.row.col.f32.tf32.tf32.f32 "
        "{%0,%1,%2,%3}, {%4,%5,%6,%7}, {%8,%9}, {%0,%1,%2,%3};"
        : "+f"(d[0]), "+f"(d[1]), "+f"(d[2]), "+f"(d[3])
        : "r"(a0), "r"(a1), "r"(a2), "r"(a3), "r"(b0), "r"(b1));
}

// ---------------------------------------------------------------------------
// Kernel 0: W -> tf32-rounded, pair-interleaved gW2 (512 KB, L2-resident)
// ---------------------------------------------------------------------------
__global__ void conv_w2(const float* __restrict__ W) {
    int pi = blockIdx.x * 256 + threadIdx.x;          // over 65536 pairs
    #pragma unroll
    for (int it = 0; it < 4; it++, pi += 16384) {
        int p = pi & 15, e = (pi >> 4) & 63, c = pi >> 10;
        int s = p >> 2, j = p & 3;
        int k = c * BK + s * 8 + j;
        float2 v;
        v.x = __uint_as_float(tf32_rna(W[e * D_MODEL + k]));
        v.y = __uint_as_float(tf32_rna(W[e * D_MODEL + k + 4]));
        gW2[pi] = v;
    }
}

// ---------------------------------------------------------------------------
// Kernel 1: single-pass tf32 GEMM (double-buffered smem, BM=128) +
// top-4 gap test + in-CTA fp64 refinement.
// ---------------------------------------------------------------------------
__global__ __launch_bounds__(THREADS)
void router_fused(const float* __restrict__ X, const float* __restrict__ W,
                  const float* __restrict__ bias, float* __restrict__ out) {
    extern __shared__ __align__(16) char smem[];
    float* bias_s = (float*)(smem + SM_BIAS);
    char*  bufs   = smem + SM_BUF;

    const int tid  = threadIdx.x;
    const int wid  = tid >> 5;
    const int lane = tid & 31;
    const int grp  = lane >> 2;     // 0..7
    const int qid  = lane & 3;      // 0..3
    const int token0 = blockIdx.x * BM;
    const int r0 = wid * 16 + grp;  // warp tile: 16 tokens x 64 experts

    // A slots: 4 per thread. id = r*256+tid -> row = id>>3, u = id&7
    // unit u covers pairs 2u, 2u+1: cols {s8+jj, s8+jj+4, s8+jj+1, s8+jj+5},
    // s = u>>1, jj = (u&1)*2
    int aRow[4], aCol[4], aU[4];
    #pragma unroll
    for (int r = 0; r < 4; r++) {
        int id = r * THREADS + tid;
        aRow[r] = id >> 3;
        int u = id & 7;
        aU[r] = u;
        aCol[r] = (u >> 1) * 8 + (u & 1) * 2;   // base col of v0
    }
    // B slots: 2 per thread. id -> e = id>>3, u = id&7 (16B unit per row)
    const int eB[2] = { (0*THREADS+tid)>>3, (1*THREADS+tid)>>3 };
    const int uB    = tid & 7;

    if (tid < NUM_EXPERTS) bias_s[tid] = bias[tid];

    float acc[8][4];
    #pragma unroll
    for (int n = 0; n < 8; n++)
        #pragma unroll
        for (int r = 0; r < 4; r++) acc[n][r] = 0.0f;

    float2 xa0[4], xa1[4];      // A staging: v0 (cols jj,jj+1), v1 (cols jj+4,jj+5)
    float4 xb[2];               // B staging (already-converted 16B units)

    // helpers to load/store one chunk
    #define LOAD_A(k0)                                                          \
        _Pragma("unroll")                                                       \
        for (int r = 0; r < 4; r++) {                                           \
            const float* xp = X + (size_t)(token0 + aRow[r]) * D_MODEL + (k0) + aCol[r]; \
            xa0[r] = *(const float2*)xp;                                        \
            xa1[r] = *(const float2*)(xp + 4);                                  \
        }
    #define LOAD_B(c)                                                           \
        _Pragma("unroll")                                                       \
        for (int r = 0; r < 2; r++)                                             \
            xb[r] = *(const float4*)((const char*)gW2 +                         \
                     ((size_t)(c) * 64 + eB[r]) * 128 + uB * 16);
    #define STORE_CHUNK(dst)                                                    \
        _Pragma("unroll")                                                       \
        for (int r = 0; r < 4; r++) {                                           \
            uint4 uv;                                                           \
            uv.x = tf32_rna(xa0[r].x); uv.y = tf32_rna(xa1[r].x);               \
            uv.z = tf32_rna(xa0[r].y); uv.w = tf32_rna(xa1[r].y);               \
            *(uint4*)((dst) + aRow[r] * ROWB + aU[r] * 16) = uv;                \
        }                                                                       \
        _Pragma("unroll")                                                       \
        for (int r = 0; r < 2; r++)                                             \
            *(float4*)((dst) + ASIZE + eB[r] * ROWB + uB * 16) = xb[r];

    // prologue: chunk 0 -> buf0 ; chunk 1 -> regs
    LOAD_A(0); LOAD_B(0);
    STORE_CHUNK(bufs);
    LOAD_A(BK); LOAD_B(1);
    __syncthreads();

    #pragma unroll 1
    for (int c = 0; c < NCHUNK; c++) {
        char* cur = bufs + (c & 1) * BUFSTRIDE;
        char* nxt = bufs + ((c + 1) & 1) * BUFSTRIDE;

        if (c + 1 < NCHUNK) { STORE_CHUNK(nxt); }
        if (c + 2 < NCHUNK) { LOAD_A((c + 2) * BK); LOAD_B(c + 2); }

        const char* As = cur;
        const char* Bs = cur + ASIZE;
        #pragma unroll
        for (int s = 0; s < 4; s++) {
            const int p = s * 4 + qid;
            uint2 a02 = lds_u2(As, r0,     p);   // a0 = col qid, a2 = col qid+4
            uint2 a13 = lds_u2(As, r0 + 8, p);
            #pragma unroll
            for (int n = 0; n < 8; n++) {
                uint2 b = lds_u2(Bs, n * 8 + grp, p);   // b0 = k qid, b1 = k qid+4
                mma_tf32(acc[n], a02.x, a13.x, a02.y, a13.y, b.x, b.y);
            }
        }
        __syncthreads();
    }

    // ------------------------------------------------------------------
    // epilogue: stage logits, per-token top-4 scan, gap test
    // ------------------------------------------------------------------
    float* L     = (float*)(smem + SM_BUF);      // L[t][e] at t*LSTRIDE+e
    int*   flags = (int*)(smem + SM_FLAGS);

    #pragma unroll
    for (int n = 0; n < 8; n++) {
        int e0 = n * 8 + 2 * qid;
        L[r0 * LSTRIDE + e0]           = acc[n][0];
        L[r0 * LSTRIDE + e0 + 1]       = acc[n][1];
        L[(r0 + 8) * LSTRIDE + e0]     = acc[n][2];
        L[(r0 + 8) * LSTRIDE + e0 + 1] = acc[n][3];
    }
    if (tid == 0) flags[0] = 0;
    __syncthreads();

    if (tid < BM) {
        const float* Lr = L + tid * LSTRIDE;
        float tv0 = -1e30f, tv1 = -1e30f, tv2 = -1e30f, tv3 = -1e30f;
        int   ti0 = 0, ti1 = 0, ti2 = 0, ti3 = 0;
        #pragma unroll
        for (int e = 0; e < NUM_EXPERTS; e++) {
            float v = Lr[e] + bias_s[e];
            if (v > tv0) {
                tv3 = tv2; ti3 = ti2; tv2 = tv1; ti2 = ti1;
                tv1 = tv0; ti1 = ti0; tv0 = v;  ti0 = e;
            } else if (v > tv1) {
                tv3 = tv2; ti3 = ti2; tv2 = tv1; ti2 = ti1; tv1 = v; ti1 = e;
            } else if (v > tv2) {
                tv3 = tv2; ti3 = ti2; tv2 = v;  ti2 = e;
            } else if (v > tv3) {
                tv3 = v; ti3 = e;
            }
        }
        const int token = token0 + tid;
        if ((tv0 - tv1) < GAP_THRESH || (tv1 - tv2) < GAP_THRESH) {
            int idx = atomicAdd(&flags[0], 1);
            int* rec = &flags[1 + idx * 5];
            rec[0] = token; rec[1] = ti0; rec[2] = ti1; rec[3] = ti2; rec[4] = ti3;
        } else {
            float r  = expf(tv1 - tv0);
            out[token * 2 + 0] = 1.0f / (1.0f + r);
            out[token * 2 + 1] = r / (1.0f + r);
            out[N_TOKENS * 2 + token * 2 + 0] = (float)ti0;
            out[N_TOKENS * 2 + token * 2 + 1] = (float)ti1;
        }
    }
    __syncthreads();

    // ------------------------------------------------------------------
    // in-CTA fp64 refinement of flagged tokens (one warp per record)
    // ------------------------------------------------------------------
    const int nrec = flags[0];
    for (int r = wid; r < nrec; r += 8) {
        const int* rec = &flags[1 + r * 5];
        const int token = rec[0];
        const float* xr = X + (size_t)token * D_MODEL;
        const float* w0 = W + (size_t)rec[1] * D_MODEL;
        const float* w1 = W + (size_t)rec[2] * D_MODEL;
        const float* w2 = W + (size_t)rec[3] * D_MODEL;
        const float* w3 = W + (size_t)rec[4] * D_MODEL;

        double a0[4] = {0, 0, 0, 0}, a1[4] = {0, 0, 0, 0};
        #pragma unroll 4
        for (int k = lane; k < D_MODEL; k += 64) {
            double x0 = (double)xr[k], x1 = (double)xr[k + 32];
            a0[0] += x0 * (double)w0[k];  a1[0] += x1 * (double)w0[k + 32];
            a0[1] += x0 * (double)w1[k];  a1[1] += x1 * (double)w1[k + 32];
            a0[2] += x0 * (double)w2[k];  a1[2] += x1 * (double)w2[k + 32];
            a0[3] += x0 * (double)w3[k];  a1[3] += x1 * (double)w3[k + 32];
        }
        double lv[4];
        #pragma unroll
        for (int cc = 0; cc < 4; cc++) {
            double s = a0[cc] + a1[cc];
            #pragma unroll
            for (int off = 16; off; off >>= 1)
                s += __shfl_down_sync(0xffffffffu, s, off);
            lv[cc] = s + (double)bias_s[rec[1 + cc]];
        }
        if (lane == 0) {
            int ei[4] = {rec[1], rec[2], rec[3], rec[4]};
            #pragma unroll
            for (int i = 1; i < 4; i++) {        // insertion sort desc, tie->lower idx
                double v = lv[i]; int id = ei[i];
                int j = i - 1;
                while (j >= 0 && (lv[j] < v || (lv[j] == v && ei[j] > id))) {
                    lv[j + 1] = lv[j]; ei[j + 1] = ei[j]; j--;
                }
                lv[j + 1] = v; ei[j + 1] = id;
            }
            double rr = exp(lv[1] - lv[0]);
            out[token * 2 + 0] = (float)(1.0 / (1.0 + rr));
            out[token * 2 + 1] = (float)(rr / (1.0 + rr));
            out[N_TOKENS * 2 + token * 2 + 0] = (float)ei[0];
            out[N_TOKENS * 2 + token * 2 + 1] = (float)ei[1];
        }
    }
}

// ---------------------------------------------------------------------------
extern "C" void kernel_launch(void* const* d_in, const int* in_sizes, int n_in,
                              void* d_out, int out_size) {
    const float* X = (const float*)d_in[0];   // [4, 4096, 2048]
    const float* W = (const float*)d_in[1];   // [64, 2048]
    const float* b = (const float*)d_in[2];   // [64]
    float* out = (float*)d_out;

    static int configured = 0;
    if (!configured) {
        cudaFuncSetAttribute(router_fused,
                             cudaFuncAttributeMaxDynamicSharedMemorySize, SMEM_TOTAL);
        configured = 1;
    }
    conv_w2<<<64, 256>>>(W);
    router_fused<<<N_TOKENS / BM, THREADS, SMEM_TOTAL>>>(X, W, b, out);
}